// round 8
// baseline (speedup 1.0000x reference)
#include <cuda_runtime.h>
#include <cstdint>

// Problem constants
#define MAXN 100000
#define MAXE 3200000
#define FDIM 7
#define HDIM 128
#define DDIM 64
#define EPSV 1e-5f

// Scratch (__device__ globals; allocation-free rule)
__device__ float g_bufA[MAXN * HDIM];   // running node features h [N,128]
__device__ float g_bufB[MAXN * HDIM];   // h @ W (stride = DO of current layer)
__device__ float g_dinv[MAXN];
__device__ int   g_rowptr[MAXN + 1];    // CSR row pointers over dst
__device__ int   g_fill[MAXN];          // scatter cursors
__device__ int   g_srcidx[MAXE];        // CSR: src node per incoming edge
__device__ float g_coef[MAXE];          // CSR: dinv[src]*dinv[dst] per edge

// ---------------------------------------------------------------------------
// CSR build  (edge_index is INT32: row 0 = src[0..E), row 1 = dst[0..E))
// ---------------------------------------------------------------------------
__global__ void zero_rowptr_kernel(int n1) {
    int i = blockIdx.x * blockDim.x + threadIdx.x;
    if (i < n1) g_rowptr[i] = 0;
}

__global__ void hist_kernel(const int* __restrict__ ei, int E_) {
    int e = blockIdx.x * blockDim.x + threadIdx.x;
    if (e < E_) {
        int dst = ei[E_ + e];
        atomicAdd(&g_rowptr[dst + 1], 1);   // INT atomic (safe on sm_103a)
    }
}

// in-place inclusive scan over rowptr[0..n) — one block, 1024 threads
__global__ void scan_kernel(int n) {
    __shared__ int part[1024];
    int t = threadIdx.x;
    int C = (n + 1023) / 1024;
    int b = t * C;
    int e = b + C; if (e > n) e = n;
    int s = 0;
    for (int i = b; i < e; i++) s += g_rowptr[i];
    part[t] = s;
    __syncthreads();
    if (t == 0) {
        int run = 0;
        for (int i = 0; i < 1024; i++) { int x = part[i]; part[i] = run; run += x; }
    }
    __syncthreads();
    int run = part[t];
    for (int i = b; i < e; i++) { run += g_rowptr[i]; g_rowptr[i] = run; }
}

// dinv from degrees (+1 self-loop); also init fill cursors
__global__ void dinv_fill_kernel(int n) {
    int i = blockIdx.x * blockDim.x + threadIdx.x;
    if (i < n) {
        int beg = g_rowptr[i];
        int deg = g_rowptr[i + 1] - beg;
        g_dinv[i] = rsqrtf((float)deg + 1.0f);
        g_fill[i] = beg;
    }
}

__global__ void scatter_kernel(const int* __restrict__ ei, int E_) {
    int e = blockIdx.x * blockDim.x + threadIdx.x;
    if (e < E_) {
        int src = ei[e];
        int dst = ei[E_ + e];
        int pos = atomicAdd(&g_fill[dst], 1);   // INT atomic
        g_srcidx[pos] = src;
        g_coef[pos] = g_dinv[src] * g_dinv[dst];
    }
}

// ---------------------------------------------------------------------------
// input projection: bufA = relu(x @ W_in + b_in)   x:[N,7] W:[7,128]
// ---------------------------------------------------------------------------
__global__ void inproj_kernel(const float* __restrict__ x,
                              const float* __restrict__ W,
                              const float* __restrict__ b,
                              int n) {
    int i = blockIdx.x * blockDim.x + threadIdx.x;
    if (i >= n * HDIM) return;
    int node = i >> 7;
    int c = i & 127;
    float s = b[c];
#pragma unroll
    for (int k = 0; k < FDIM; k++)
        s = fmaf(x[node * FDIM + k], W[k * HDIM + c], s);
    g_bufA[i] = fmaxf(s, 0.0f);
}

// ---------------------------------------------------------------------------
// GEMM: bufB = bufA @ W   A:[n,128], W:[128,DO], bufB stride DO
// 64 rows x DO cols per block, 256 threads.
// ---------------------------------------------------------------------------
template <int DO>
__global__ void gemm_kernel(const float* __restrict__ W, int n) {
    constexpr int DI = HDIM;
    constexpr int TM = 64;
    constexpr int CT = DO / 4;        // threads along columns (float4)
    constexpr int RT = 256 / CT;      // threads along rows
    constexpr int RM = TM / RT;       // rows per thread
    constexpr int LDA = DI + 1;       // padded smem stride

    __shared__ float Asm[TM * LDA];

    int m0 = blockIdx.x * TM;
    int tid = threadIdx.x;

    for (int idx = tid; idx < TM * DI; idx += 256) {
        int r = idx >> 7;             // DI = 128
        int c = idx & 127;
        int gr = m0 + r;
        Asm[r * LDA + c] = (gr < n) ? g_bufA[(size_t)gr * DI + c] : 0.0f;
    }
    __syncthreads();

    int ct = tid % CT;
    int ry = tid / CT;
    int c0 = ct * 4;

    float acc[RM][4];
#pragma unroll
    for (int j = 0; j < RM; j++) {
        acc[j][0] = 0.f; acc[j][1] = 0.f; acc[j][2] = 0.f; acc[j][3] = 0.f;
    }

#pragma unroll 8
    for (int k = 0; k < DI; k++) {
        float4 wv = *reinterpret_cast<const float4*>(&W[k * DO + c0]);
#pragma unroll
        for (int j = 0; j < RM; j++) {
            float a = Asm[(ry + RT * j) * LDA + k];
            acc[j][0] = fmaf(a, wv.x, acc[j][0]);
            acc[j][1] = fmaf(a, wv.y, acc[j][1]);
            acc[j][2] = fmaf(a, wv.z, acc[j][2]);
            acc[j][3] = fmaf(a, wv.w, acc[j][3]);
        }
    }

#pragma unroll
    for (int j = 0; j < RM; j++) {
        int node = m0 + ry + RT * j;
        if (node < n) {
            float4 o;
            o.x = acc[j][0]; o.y = acc[j][1]; o.z = acc[j][2]; o.w = acc[j][3];
            *reinterpret_cast<float4*>(&g_bufB[(size_t)node * DO + c0]) = o;
        }
    }
}

// ---------------------------------------------------------------------------
// Fused gather: for each node, agg = sum_in coef*bufB[src] + bufB[node]*dinv^2
//               + bias, then BN (+relu+residual for hidden layers).
// One lane per (node, 4-col chunk). NO atomics, NO float reds.
// ---------------------------------------------------------------------------
template <int DO, bool FINAL>
__global__ void gather_kernel(const float* __restrict__ bias,
                              const float* __restrict__ g,
                              const float* __restrict__ be,
                              const float* __restrict__ m,
                              const float* __restrict__ v,
                              float* __restrict__ out,
                              int n) {
    constexpr int LPN = DO / 4;       // lanes per node
    int gt = blockIdx.x * blockDim.x + threadIdx.x;
    int node = gt / LPN;
    int c = gt - node * LPN;
    if (node >= n) return;
    int c0 = c * 4;

    const float4* Bv = reinterpret_cast<const float4*>(g_bufB);

    float dv = g_dinv[node];
    float d2 = dv * dv;

    float4 hv = Bv[(size_t)node * LPN + c];
    float4 acc;
    acc.x = fmaf(hv.x, d2, bias[c0 + 0]);
    acc.y = fmaf(hv.y, d2, bias[c0 + 1]);
    acc.z = fmaf(hv.z, d2, bias[c0 + 2]);
    acc.w = fmaf(hv.w, d2, bias[c0 + 3]);

    int j = g_rowptr[node];
    int end = g_rowptr[node + 1];

    // unroll-by-4 for MLP against L2 latency
    for (; j + 4 <= end; j += 4) {
        int s0 = g_srcidx[j + 0], s1 = g_srcidx[j + 1];
        int s2 = g_srcidx[j + 2], s3 = g_srcidx[j + 3];
        float k0 = g_coef[j + 0], k1 = g_coef[j + 1];
        float k2 = g_coef[j + 2], k3 = g_coef[j + 3];
        float4 v0 = Bv[(size_t)s0 * LPN + c];
        float4 v1 = Bv[(size_t)s1 * LPN + c];
        float4 v2 = Bv[(size_t)s2 * LPN + c];
        float4 v3 = Bv[(size_t)s3 * LPN + c];
        acc.x = fmaf(k0, v0.x, acc.x); acc.y = fmaf(k0, v0.y, acc.y);
        acc.z = fmaf(k0, v0.z, acc.z); acc.w = fmaf(k0, v0.w, acc.w);
        acc.x = fmaf(k1, v1.x, acc.x); acc.y = fmaf(k1, v1.y, acc.y);
        acc.z = fmaf(k1, v1.z, acc.z); acc.w = fmaf(k1, v1.w, acc.w);
        acc.x = fmaf(k2, v2.x, acc.x); acc.y = fmaf(k2, v2.y, acc.y);
        acc.z = fmaf(k2, v2.z, acc.z); acc.w = fmaf(k2, v2.w, acc.w);
        acc.x = fmaf(k3, v3.x, acc.x); acc.y = fmaf(k3, v3.y, acc.y);
        acc.z = fmaf(k3, v3.z, acc.z); acc.w = fmaf(k3, v3.w, acc.w);
    }
    for (; j < end; j++) {
        int s = g_srcidx[j];
        float k = g_coef[j];
        float4 vv = Bv[(size_t)s * LPN + c];
        acc.x = fmaf(k, vv.x, acc.x); acc.y = fmaf(k, vv.y, acc.y);
        acc.z = fmaf(k, vv.z, acc.z); acc.w = fmaf(k, vv.w, acc.w);
    }

    // BN: val = acc*scale + shift, scale = g*rsqrt(v+eps), shift = be - m*scale
    float sx = g[c0 + 0] * rsqrtf(v[c0 + 0] + EPSV);
    float sy = g[c0 + 1] * rsqrtf(v[c0 + 1] + EPSV);
    float sz = g[c0 + 2] * rsqrtf(v[c0 + 2] + EPSV);
    float sw = g[c0 + 3] * rsqrtf(v[c0 + 3] + EPSV);
    float4 val;
    val.x = fmaf(acc.x, sx, fmaf(-m[c0 + 0], sx, be[c0 + 0]));
    val.y = fmaf(acc.y, sy, fmaf(-m[c0 + 1], sy, be[c0 + 1]));
    val.z = fmaf(acc.z, sz, fmaf(-m[c0 + 2], sz, be[c0 + 2]));
    val.w = fmaf(acc.w, sw, fmaf(-m[c0 + 3], sw, be[c0 + 3]));

    if (FINAL) {
        *reinterpret_cast<float4*>(&out[(size_t)node * DO + c0]) = val;
    } else {
        float4* Ap = reinterpret_cast<float4*>(&g_bufA[(size_t)node * HDIM + c0]);
        float4 old = *Ap;
        val.x = fmaxf(val.x, 0.0f) + old.x;
        val.y = fmaxf(val.y, 0.0f) + old.y;
        val.z = fmaxf(val.z, 0.0f) + old.z;
        val.w = fmaxf(val.w, 0.0f) + old.w;
        *Ap = val;
    }
}

// ---------------------------------------------------------------------------
extern "C" void kernel_launch(void* const* d_in, const int* in_sizes, int n_in,
                              void* d_out, int out_size) {
    const float* x    = (const float*)d_in[0];
    const int*   ei   = (const int*)d_in[1];      // int32 edge_index [2,E]
    const float* W_in = (const float*)d_in[2];
    const float* b_in = (const float*)d_in[3];

    const float* W0  = (const float*)d_in[4];
    const float* b0  = (const float*)d_in[5];
    const float* g0  = (const float*)d_in[6];
    const float* be0 = (const float*)d_in[7];
    const float* m0  = (const float*)d_in[8];
    const float* v0  = (const float*)d_in[9];

    const float* W1  = (const float*)d_in[10];
    const float* b1  = (const float*)d_in[11];
    const float* g1  = (const float*)d_in[12];
    const float* be1 = (const float*)d_in[13];
    const float* m1  = (const float*)d_in[14];
    const float* v1  = (const float*)d_in[15];

    const float* W2  = (const float*)d_in[16];
    const float* b2  = (const float*)d_in[17];
    const float* g2  = (const float*)d_in[18];
    const float* be2 = (const float*)d_in[19];
    const float* m2  = (const float*)d_in[20];
    const float* v2  = (const float*)d_in[21];

    int N_ = in_sizes[0] / FDIM;
    int E_ = in_sizes[1] / 2;
    float* out = (float*)d_out;

    const int T = 256;

    // ---- CSR build (int atomics only) ----
    zero_rowptr_kernel<<<(N_ + 1 + T - 1) / T, T>>>(N_ + 1);
    hist_kernel<<<(E_ + T - 1) / T, T>>>(ei, E_);
    scan_kernel<<<1, 1024>>>(N_ + 1);
    dinv_fill_kernel<<<(N_ + T - 1) / T, T>>>(N_);
    scatter_kernel<<<(E_ + T - 1) / T, T>>>(ei, E_);

    // ---- input projection ----
    inproj_kernel<<<((size_t)N_ * HDIM + T - 1) / T, T>>>(x, W_in, b_in, N_);

    int gemm_blocks = (N_ + 63) / 64;
    int gat128_blocks = (int)(((size_t)N_ * (HDIM / 4) + T - 1) / T);
    int gat64_blocks  = (int)(((size_t)N_ * (DDIM / 4) + T - 1) / T);

    // ---- layer 0 (128 -> 128) ----
    gemm_kernel<HDIM><<<gemm_blocks, 256>>>(W0, N_);
    gather_kernel<HDIM, false><<<gat128_blocks, T>>>(b0, g0, be0, m0, v0, nullptr, N_);

    // ---- layer 1 (128 -> 128) ----
    gemm_kernel<HDIM><<<gemm_blocks, 256>>>(W1, N_);
    gather_kernel<HDIM, false><<<gat128_blocks, T>>>(b1, g1, be1, m1, v1, nullptr, N_);

    // ---- layer 2 (128 -> 64), BN only ----
    gemm_kernel<DDIM><<<gemm_blocks, 256>>>(W2, N_);
    gather_kernel<DDIM, true><<<gat64_blocks, T>>>(b2, g2, be2, m2, v2, out, N_);
}